// round 1
// baseline (speedup 1.0000x reference)
#include <cuda_runtime.h>

// VectorQuantizer: input (16, 64, 8192) fp32, codebook (1024, 64) fp32
// out = codebook[argmin_k ||x - e_k||^2] scattered back to (B, D, T), plus indices.

#define Dd 64
#define Kk 1024
#define Bb 16
#define Tt 8192
#define Nn (Bb * Tt)          // 131072 tokens
#define TPB 256               // threads per block
#define TOKS_PER_BLOCK (2 * TPB)
#define CK 128                // codes per smem chunk (128*64*4 = 32 KB)
#define NCHUNK (Kk / CK)

__device__ float g_half_sq[Kk];

// ---- packed f32x2 helpers (Blackwell-only double-rate fp32 FMA) ----
__device__ __forceinline__ unsigned long long pk2(float a, float b) {
    unsigned long long r;
    asm("mov.b64 %0, {%1, %2};" : "=l"(r) : "f"(a), "f"(b));
    return r;
}
__device__ __forceinline__ void fma2(unsigned long long& acc,
                                     unsigned long long a, unsigned long long b) {
    asm("fma.rn.f32x2 %0, %1, %2, %0;" : "+l"(acc) : "l"(a), "l"(b));
}
__device__ __forceinline__ unsigned long long add2(unsigned long long a,
                                                   unsigned long long b) {
    unsigned long long r;
    asm("add.rn.f32x2 %0, %1, %2;" : "=l"(r) : "l"(a), "l"(b));
    return r;
}
__device__ __forceinline__ float hsum2(unsigned long long v) {
    float lo, hi;
    asm("mov.b64 {%0, %1}, %2;" : "=f"(lo), "=f"(hi) : "l"(v));
    return lo + hi;
}

// Precompute 0.5*||e_k||^2 for every code.
__global__ void vq_pre(const float* __restrict__ cb) {
    int k = blockIdx.x * blockDim.x + threadIdx.x;
    if (k >= Kk) return;
    const float4* row = reinterpret_cast<const float4*>(cb + k * Dd);
    float s = 0.f;
#pragma unroll
    for (int i = 0; i < Dd / 4; i++) {
        float4 v = row[i];
        s += v.x * v.x + v.y * v.y + v.z * v.z + v.w * v.w;
    }
    g_half_sq[k] = 0.5f * s;
}

__global__ __launch_bounds__(TPB, 1)
void vq_main(const float* __restrict__ input, const float* __restrict__ cb,
             float* __restrict__ out, float* __restrict__ out_idx) {
    __shared__ float sCode[CK * Dd];   // 32 KB chunk of codebook
    __shared__ float sHalf[Kk];        // 4 KB: 0.5*||e||^2 for all codes

    const int tid = threadIdx.x;
    const long n0 = (long)blockIdx.x * TOKS_PER_BLOCK + tid;   // token 0
    // token 1 = n0 + TPB; block spans 512 tokens, 8192 % 512 == 0 -> same batch b
    const int b  = (int)(n0 >> 13);          // /8192
    const int t0 = (int)(n0 & (Tt - 1));
    const int t1 = t0 + TPB;
    const float* base = input + (long)b * Dd * Tt;

    // Load both tokens' feature vectors, packed along D:
    // x[i] = {x[2i], x[2i+1]} so smem e-pairs can be consumed as raw 64-bit words.
    unsigned long long x0[Dd / 2], x1[Dd / 2];
#pragma unroll
    for (int i = 0; i < Dd / 2; i++) {
        float a0 = base[(long)(2 * i) * Tt + t0];
        float b0 = base[(long)(2 * i + 1) * Tt + t0];
        x0[i] = pk2(a0, b0);
        float a1 = base[(long)(2 * i) * Tt + t1];
        float b1 = base[(long)(2 * i + 1) * Tt + t1];
        x1[i] = pk2(a1, b1);
    }

    for (int i = tid; i < Kk; i += TPB) sHalf[i] = g_half_sq[i];

    float best0 = 3.4e38f, best1 = 3.4e38f;
    int bi0 = 0, bi1 = 0;

    for (int c = 0; c < NCHUNK; c++) {
        __syncthreads();
        const float4* src = reinterpret_cast<const float4*>(cb + (long)c * CK * Dd);
        float4* dst = reinterpret_cast<float4*>(sCode);
        for (int i = tid; i < CK * Dd / 4; i += TPB) dst[i] = src[i];
        __syncthreads();

#pragma unroll 1
        for (int k = 0; k < CK; k++) {
            const ulonglong2* er = reinterpret_cast<const ulonglong2*>(sCode + k * Dd);
            unsigned long long a00 = 0, a01 = 0, a10 = 0, a11 = 0;
#pragma unroll
            for (int j = 0; j < 16; j++) {
                ulonglong2 e = er[j];           // LDS.128 broadcast: two packed e-pairs
                fma2(a00, x0[2 * j],     e.x);
                fma2(a01, x0[2 * j + 1], e.y);
                fma2(a10, x1[2 * j],     e.x);
                fma2(a11, x1[2 * j + 1], e.y);
            }
            const int kk = c * CK + k;
            const float hs = sHalf[kk];
            // score = 0.5||e||^2 - x.e  (argmin-equivalent to full distance)
            float s0 = hs - hsum2(add2(a00, a01));
            float s1 = hs - hsum2(add2(a10, a11));
            if (s0 < best0) { best0 = s0; bi0 = kk; }   // strict < : first-occurrence ties
            if (s1 < best1) { best1 = s1; bi1 = kk; }
        }
    }

    // Scatter selected code vectors back to (B, D, T) layout.
    // Consecutive tid -> consecutive t, so each STG is warp-coalesced.
    float* ob = out + (long)b * Dd * Tt;
    const float4* c0 = reinterpret_cast<const float4*>(cb + (long)bi0 * Dd);
    const float4* c1 = reinterpret_cast<const float4*>(cb + (long)bi1 * Dd);
#pragma unroll
    for (int i = 0; i < Dd / 4; i++) {
        float4 v0 = c0[i];
        float4 v1 = c1[i];
        ob[(long)(4 * i + 0) * Tt + t0] = v0.x;
        ob[(long)(4 * i + 1) * Tt + t0] = v0.y;
        ob[(long)(4 * i + 2) * Tt + t0] = v0.z;
        ob[(long)(4 * i + 3) * Tt + t0] = v0.w;
        ob[(long)(4 * i + 0) * Tt + t1] = v1.x;
        ob[(long)(4 * i + 1) * Tt + t1] = v1.y;
        ob[(long)(4 * i + 2) * Tt + t1] = v1.z;
        ob[(long)(4 * i + 3) * Tt + t1] = v1.w;
    }

    if (out_idx != nullptr) {
        out_idx[n0]       = (float)bi0;
        out_idx[n0 + TPB] = (float)bi1;
    }
}

extern "C" void kernel_launch(void* const* d_in, const int* in_sizes, int n_in,
                              void* d_out, int out_size) {
    const float* input = (const float*)d_in[0];   // (16, 64, 8192) fp32
    const float* cb    = (const float*)d_in[1];   // (1024, 64) fp32
    float* out = (float*)d_out;

    // Reference returns (out, idx). If the output buffer covers both, write
    // indices (as float) after the quantized block; otherwise out only.
    float* out_idx = nullptr;
    if (out_size >= (int)((long)Nn * Dd + Nn)) {
        out_idx = out + (long)Nn * Dd;
    }

    vq_pre<<<(Kk + 255) / 256, 256>>>(cb);
    vq_main<<<Nn / TOKS_PER_BLOCK, TPB>>>(input, cb, out, out_idx);
}